// round 1
// baseline (speedup 1.0000x reference)
#include <cuda_runtime.h>
#include <cuda_bf16.h>
#include <cstdint>

#define N_NODES 50000
#define N_EDGES 800000
#define N_GRAPHS 64
#define HEADS 8
#define NEG_SLOPE 0.2f

// ---------------- scratch (device globals; no allocations allowed) ----------
static __device__ float g_xp[(size_t)N_NODES * 2048];   // per-layer projected features (max 8*256)
static __device__ float g_h[(size_t)N_NODES * 256];     // inter-layer node features
static __device__ float g_als[N_NODES * HEADS];
static __device__ float g_ald[N_NODES * HEADS];
static __device__ float g_alpha[(size_t)N_EDGES * HEADS];
static __device__ float g_aself[N_NODES * HEADS];
static __device__ int   g_deg[N_NODES];
static __device__ int   g_rowptr[N_NODES + 1];
static __device__ int   g_cursor[N_NODES];
static __device__ int   g_csrc[N_EDGES];
static __device__ float g_gmean[N_GRAPHS * 256];

__device__ __forceinline__ float leakyf(float x) {
    return x > 0.f ? x : NEG_SLOPE * x;
}
__device__ __forceinline__ float eluf(float x) {
    return x > 0.f ? x : (__expf(x) - 1.f);
}

// ---------------- CSR build --------------------------------------------------
__global__ void k_zero_deg() {
    int i = blockIdx.x * blockDim.x + threadIdx.x;
    if (i < N_NODES) g_deg[i] = 0;
}

__global__ void k_hist(const int* __restrict__ dst) {
    int e = blockIdx.x * blockDim.x + threadIdx.x;
    if (e < N_EDGES) atomicAdd(&g_deg[dst[e]], 1);
}

__global__ void k_scan() {   // single block, 1024 threads
    __shared__ int sm[1024];
    __shared__ int carry;
    int t = threadIdx.x;
    if (t == 0) carry = 0;
    __syncthreads();
    for (int base = 0; base < N_NODES; base += 1024) {
        int i = base + t;
        int v = (i < N_NODES) ? g_deg[i] : 0;
        sm[t] = v;
        __syncthreads();
        for (int off = 1; off < 1024; off <<= 1) {
            int x = (t >= off) ? sm[t - off] : 0;
            __syncthreads();
            sm[t] += x;
            __syncthreads();
        }
        int excl = sm[t] - v;
        int total = sm[1023];
        if (i < N_NODES) { g_rowptr[i] = carry + excl; g_cursor[i] = carry + excl; }
        __syncthreads();
        if (t == 0) carry += total;
        __syncthreads();
    }
    if (t == 0) g_rowptr[N_NODES] = N_EDGES;
}

__global__ void k_scatter(const int* __restrict__ src, const int* __restrict__ dst) {
    int e = blockIdx.x * blockDim.x + threadIdx.x;
    if (e < N_EDGES) {
        int d = dst[e];
        int pos = atomicAdd(&g_cursor[d], 1);
        g_csrc[pos] = src[e];
    }
}

// ---------------- SGEMM: C[M,N] = A[M,K] * B[N,K]^T --------------------------
#define BM 128
#define BN 128
#define BK 8
#define TM 8
#define TN 8
__global__ __launch_bounds__(256) void k_sgemm_nt(
    const float* __restrict__ A, const float* __restrict__ B,
    float* __restrict__ C, int M, int N, int K)
{
    __shared__ float As[BK][BM + 4];
    __shared__ float Bs[BK][BN + 4];
    int tid = threadIdx.x;
    int m0 = blockIdx.y * BM;
    int n0 = blockIdx.x * BN;
    int trow = (tid / 16) * TM;
    int tcol = (tid % 16) * TN;
    float acc[TM][TN];
#pragma unroll
    for (int i = 0; i < TM; i++)
#pragma unroll
        for (int j = 0; j < TN; j++) acc[i][j] = 0.f;

    for (int k0 = 0; k0 < K; k0 += BK) {
#pragma unroll
        for (int i = 0; i < 4; i++) {
            int idx = tid + i * 256;           // 0..1023
            int r = idx >> 3, c = idx & 7;
            int gm = m0 + r;
            As[c][r] = (gm < M) ? A[(size_t)gm * K + k0 + c] : 0.f;
            int gn = n0 + r;
            Bs[c][r] = (gn < N) ? B[(size_t)gn * K + k0 + c] : 0.f;
        }
        __syncthreads();
#pragma unroll
        for (int k = 0; k < BK; k++) {
            float ar[TM], br[TN];
#pragma unroll
            for (int i = 0; i < TM; i++) ar[i] = As[k][trow + i];
#pragma unroll
            for (int j = 0; j < TN; j++) br[j] = Bs[k][tcol + j];
#pragma unroll
            for (int i = 0; i < TM; i++)
#pragma unroll
                for (int j = 0; j < TN; j++) acc[i][j] += ar[i] * br[j];
        }
        __syncthreads();
    }
#pragma unroll
    for (int i = 0; i < TM; i++) {
        int gm = m0 + trow + i;
        if (gm >= M) continue;
#pragma unroll
        for (int j = 0; j < TN; j++) {
            int gn = n0 + tcol + j;
            if (gn < N) C[(size_t)gm * N + gn] = acc[i][j];
        }
    }
}

// ---------------- attention logits: al_s/al_d per (node, head) --------------
// block = 256 threads = 8 warps; block n; warp w -> head w; d = per-head dim
__global__ void k_al(const float* __restrict__ xp, const float* __restrict__ as_,
                     const float* __restrict__ ad_, int d)
{
    int n = blockIdx.x;
    int w = threadIdx.x >> 5, lane = threadIdx.x & 31;
    const float* row = xp + (size_t)n * (HEADS * d) + w * d;
    float s1 = 0.f, s2 = 0.f;
    for (int i = lane; i < d; i += 32) {
        float v = row[i];
        s1 += v * as_[w * d + i];
        s2 += v * ad_[w * d + i];
    }
#pragma unroll
    for (int o = 16; o; o >>= 1) {
        s1 += __shfl_down_sync(0xffffffffu, s1, o);
        s2 += __shfl_down_sync(0xffffffffu, s2, o);
    }
    if (lane == 0) {
        g_als[n * HEADS + w] = s1;
        g_ald[n * HEADS + w] = s2;
    }
}

// ---------------- edge softmax (per dst node, online) ------------------------
// warp per node; lanes 0..7 handle heads
__global__ void k_softmax() {
    int n = blockIdx.x * (blockDim.x >> 5) + (threadIdx.x >> 5);
    if (n >= N_NODES) return;
    int lane = threadIdx.x & 31;
    if (lane >= HEADS) return;
    int lo = g_rowptr[n], hi = g_rowptr[n + 1];
    float adh = g_ald[n * HEADS + lane];
    float eself = leakyf(g_als[n * HEADS + lane] + adh);
    float m = eself, den = 1.f;
    for (int p = lo; p < hi; p++) {
        int s = g_csrc[p];
        float e = leakyf(g_als[s * HEADS + lane] + adh);
        if (e > m) { den = den * __expf(m - e) + 1.f; m = e; }
        else       { den += __expf(e - m); }
    }
    float inv = 1.f / den;
    g_aself[n * HEADS + lane] = __expf(eself - m) * inv;
    for (int p = lo; p < hi; p++) {
        int s = g_csrc[p];
        float e = leakyf(g_als[s * HEADS + lane] + adh);
        g_alpha[(size_t)p * HEADS + lane] = __expf(e - m) * inv;
    }
}

// ---------------- aggregation, d=32 concat (+bias, +ELU) ---------------------
// warp per node; lane j handles dim j of every head
__global__ void k_agg32(const float* __restrict__ xp, const float* __restrict__ bias,
                        float* __restrict__ out)
{
    int n = blockIdx.x * (blockDim.x >> 5) + (threadIdx.x >> 5);
    if (n >= N_NODES) return;
    int lane = threadIdx.x & 31;
    int lo = g_rowptr[n], hi = g_rowptr[n + 1];
    float acc[HEADS];
    {
        float av = (lane < HEADS) ? g_aself[n * HEADS + lane] : 0.f;
        const float* row = xp + (size_t)n * 256;
#pragma unroll
        for (int k = 0; k < HEADS; k++)
            acc[k] = __shfl_sync(0xffffffffu, av, k) * row[k * 32 + lane];
    }
    for (int p = lo; p < hi; p++) {
        int s = g_csrc[p];
        float av = (lane < HEADS) ? g_alpha[(size_t)p * HEADS + lane] : 0.f;
        const float* row = xp + (size_t)s * 256;
#pragma unroll
        for (int k = 0; k < HEADS; k++)
            acc[k] += __shfl_sync(0xffffffffu, av, k) * row[k * 32 + lane];
    }
#pragma unroll
    for (int k = 0; k < HEADS; k++) {
        float v = acc[k] + bias[k * 32 + lane];
        out[(size_t)n * 256 + k * 32 + lane] = eluf(v);
    }
}

// ---------------- aggregation, d=256, head-mean (+bias, no ELU) --------------
// block (256 threads) per node; thread t handles dim t of every head
__global__ void k_agg_mean256(const float* __restrict__ xp, const float* __restrict__ bias,
                              float* __restrict__ out)
{
    int n = blockIdx.x;
    int t = threadIdx.x;
    __shared__ float a_sm[32][HEADS];
    __shared__ int s_sm[32];
    int lo = g_rowptr[n], hi = g_rowptr[n + 1];
    float acc[HEADS];
    {
        const float* row = xp + (size_t)n * 2048;
#pragma unroll
        for (int k = 0; k < HEADS; k++)
            acc[k] = g_aself[n * HEADS + k] * row[k * 256 + t];
    }
    for (int p0 = lo; p0 < hi; p0 += 32) {
        int cnt = min(32, hi - p0);
        __syncthreads();
        if (t < cnt) s_sm[t] = g_csrc[p0 + t];
        if (t < cnt * HEADS) a_sm[t >> 3][t & 7] = g_alpha[(size_t)p0 * HEADS + t];
        __syncthreads();
        for (int j = 0; j < cnt; j++) {
            const float* row = xp + (size_t)s_sm[j] * 2048;
#pragma unroll
            for (int k = 0; k < HEADS; k++)
                acc[k] += a_sm[j][k] * row[k * 256 + t];
        }
    }
    float s = 0.f;
#pragma unroll
    for (int k = 0; k < HEADS; k++) s += acc[k];
    out[(size_t)n * 256 + t] = s * 0.125f + bias[t];
}

// ---------------- global mean pool (batch is sorted) -------------------------
__device__ __forceinline__ int lower_bound_batch(const int* b, int val) {
    int lo = 0, hi = N_NODES;
    while (lo < hi) {
        int mid = (lo + hi) >> 1;
        if (b[mid] < val) lo = mid + 1; else hi = mid;
    }
    return lo;
}

__global__ void k_pool(const float* __restrict__ h, const int* __restrict__ batch) {
    int g = blockIdx.x;
    int t = threadIdx.x;  // 256
    int lo = lower_bound_batch(batch, g);
    int hi = lower_bound_batch(batch, g + 1);
    float s = 0.f;
    for (int n = lo; n < hi; n++) s += h[(size_t)n * 256 + t];
    float c = (float)max(hi - lo, 1);
    g_gmean[g * 256 + t] = s / c;
}

// ---------------- classifier MLP ---------------------------------------------
__global__ void k_classifier(const float* __restrict__ Wc1, const float* __restrict__ bc1,
                             const float* __restrict__ Wc2, const float* __restrict__ bc2,
                             float* __restrict__ out)
{
    int g = blockIdx.x;
    int t = threadIdx.x;  // 128
    __shared__ float z[128];
    const float* gr = g_gmean + g * 256;
    float s = bc1[t];
    for (int k = 0; k < 256; k++) s += gr[k] * Wc1[t * 256 + k];
    z[t] = eluf(s);
    __syncthreads();
    if (t < 2) {
        float o = bc2[t];
        for (int j = 0; j < 128; j++) o += z[j] * Wc2[t * 128 + j];
        out[g * 2 + t] = o;
    }
}

// ---------------- launch -----------------------------------------------------
extern "C" void kernel_launch(void* const* d_in, const int* in_sizes, int n_in,
                              void* d_out, int out_size)
{
    const float* x      = (const float*)d_in[0];
    const int*   eidx   = (const int*)d_in[1];
    const int*   batch  = (const int*)d_in[2];
    const float* W1  = (const float*)d_in[3];
    const float* as1 = (const float*)d_in[4];
    const float* ad1 = (const float*)d_in[5];
    const float* b1  = (const float*)d_in[6];
    const float* W2  = (const float*)d_in[7];
    const float* as2 = (const float*)d_in[8];
    const float* ad2 = (const float*)d_in[9];
    const float* b2  = (const float*)d_in[10];
    const float* W3  = (const float*)d_in[11];
    const float* as3 = (const float*)d_in[12];
    const float* ad3 = (const float*)d_in[13];
    const float* b3  = (const float*)d_in[14];
    const float* Wc1 = (const float*)d_in[15];
    const float* bc1 = (const float*)d_in[16];
    const float* Wc2 = (const float*)d_in[17];
    const float* bc2 = (const float*)d_in[18];
    float* out = (float*)d_out;

    const int* src = eidx;
    const int* dst = eidx + N_EDGES;

    float* xp = nullptr; cudaGetSymbolAddress((void**)&xp, g_xp);
    float* h  = nullptr; cudaGetSymbolAddress((void**)&h,  g_h);

    // CSR build (dst-indexed), reused by all 3 layers
    k_zero_deg<<<(N_NODES + 255) / 256, 256>>>();
    k_hist<<<(N_EDGES + 255) / 256, 256>>>(dst);
    k_scan<<<1, 1024>>>();
    k_scatter<<<(N_EDGES + 255) / 256, 256>>>(src, dst);

    dim3 g256(256 / BN, (N_NODES + BM - 1) / BM);
    dim3 g2048(2048 / BN, (N_NODES + BM - 1) / BM);
    int nwb = (N_NODES + 7) / 8;   // grids for warp-per-node kernels (8 warps/block)

    // ---- layer 1: GATConv(32 -> 8x32, concat) + ELU
    k_sgemm_nt<<<g256, 256>>>(x, W1, xp, N_NODES, 256, 32);
    k_al<<<N_NODES, 256>>>(xp, as1, ad1, 32);
    k_softmax<<<nwb, 256>>>();
    k_agg32<<<nwb, 256>>>(xp, b1, h);

    // ---- layer 2: GATConv(256 -> 8x32, concat) + ELU
    k_sgemm_nt<<<g256, 256>>>(h, W2, xp, N_NODES, 256, 256);
    k_al<<<N_NODES, 256>>>(xp, as2, ad2, 32);
    k_softmax<<<nwb, 256>>>();
    k_agg32<<<nwb, 256>>>(xp, b2, h);

    // ---- layer 3: GATConv(256 -> 8x256, head-mean)
    k_sgemm_nt<<<g2048, 256>>>(h, W3, xp, N_NODES, 2048, 256);
    k_al<<<N_NODES, 256>>>(xp, as3, ad3, 256);
    k_softmax<<<nwb, 256>>>();
    k_agg_mean256<<<N_NODES, 256>>>(xp, b3, h);

    // ---- pool + classifier
    k_pool<<<N_GRAPHS, 256>>>(h, batch);
    k_classifier<<<N_GRAPHS, 128>>>(Wc1, bc1, Wc2, bc2, out);
}

// round 2
// speedup vs baseline: 2.1152x; 2.1152x over previous
#include <cuda_runtime.h>
#include <cuda_bf16.h>
#include <cstdint>

#define N_NODES 50000
#define N_EDGES 800000
#define N_GRAPHS 64
#define HEADS 8
#define NEG_SLOPE 0.2f

// ---------------- scratch (device globals; no allocations allowed) ----------
static __device__ float g_xp[(size_t)N_NODES * 2048];   // projected feats / layer-3 per-head agg
static __device__ float g_h[(size_t)N_NODES * 256];     // inter-layer node features
static __device__ float g_als[N_NODES * HEADS];
static __device__ float g_ald[N_NODES * HEADS];
static __device__ float g_alpha[(size_t)N_EDGES * HEADS];
static __device__ float g_aself[N_NODES * HEADS];
static __device__ int   g_deg[N_NODES];
static __device__ int   g_rowptr[N_NODES + 1];
static __device__ int   g_cursor[N_NODES];
static __device__ int   g_csrc[N_EDGES];
static __device__ float g_gmean[N_GRAPHS * 256];
static __device__ float g_wts[HEADS * 256];             // folded a_src for layer 3
static __device__ float g_wtd[HEADS * 256];             // folded a_dst for layer 3
static __device__ float g_Wm[256 * 2048];               // rearranged W3 (mean folded in)

__device__ __forceinline__ float leakyf(float x) { return x > 0.f ? x : NEG_SLOPE * x; }
__device__ __forceinline__ float eluf(float x)   { return x > 0.f ? x : (__expf(x) - 1.f); }

__device__ __forceinline__ uint32_t f2tf32(float x) {
    uint32_t r; asm("cvt.rna.tf32.f32 %0, %1;" : "=r"(r) : "f"(x)); return r;
}
__device__ __forceinline__ void mma_tf32(float* c, const uint32_t* a, const uint32_t* b) {
    asm volatile(
        "mma.sync.aligned.m16n8k8.row.col.f32.tf32.tf32.f32 "
        "{%0,%1,%2,%3}, {%4,%5,%6,%7}, {%8,%9}, {%0,%1,%2,%3};\n"
        : "+f"(c[0]), "+f"(c[1]), "+f"(c[2]), "+f"(c[3])
        : "r"(a[0]), "r"(a[1]), "r"(a[2]), "r"(a[3]), "r"(b[0]), "r"(b[1]));
}

// ---------------- CSR build --------------------------------------------------
__global__ void k_zero_deg() {
    int i = blockIdx.x * blockDim.x + threadIdx.x;
    if (i < N_NODES) g_deg[i] = 0;
}
__global__ void k_hist(const int* __restrict__ dst) {
    int e = blockIdx.x * blockDim.x + threadIdx.x;
    if (e < N_EDGES) atomicAdd(&g_deg[dst[e]], 1);
}
__global__ void k_scan() {   // single block, 1024 threads
    __shared__ int sm[1024];
    __shared__ int carry;
    int t = threadIdx.x;
    if (t == 0) carry = 0;
    __syncthreads();
    for (int base = 0; base < N_NODES; base += 1024) {
        int i = base + t;
        int v = (i < N_NODES) ? g_deg[i] : 0;
        sm[t] = v;
        __syncthreads();
        for (int off = 1; off < 1024; off <<= 1) {
            int x = (t >= off) ? sm[t - off] : 0;
            __syncthreads();
            sm[t] += x;
            __syncthreads();
        }
        int excl = sm[t] - v;
        int total = sm[1023];
        if (i < N_NODES) { g_rowptr[i] = carry + excl; g_cursor[i] = carry + excl; }
        __syncthreads();
        if (t == 0) carry += total;
        __syncthreads();
    }
    if (t == 0) g_rowptr[N_NODES] = N_EDGES;
}
__global__ void k_scatter(const int* __restrict__ src, const int* __restrict__ dst) {
    int e = blockIdx.x * blockDim.x + threadIdx.x;
    if (e < N_EDGES) {
        int d = dst[e];
        int pos = atomicAdd(&g_cursor[d], 1);
        g_csrc[pos] = src[e];
    }
}

// ---------------- tf32 tensor-core GEMM: C[M,N] = A[M,K] * B[N,K]^T (+bias) --
#define GBM 128
#define GBN 128
#define GBK 16
#define SST 20   // smem row stride (floats): conflict-free for the frag pattern

__global__ __launch_bounds__(256) void k_mma_nt(
    const float* __restrict__ A, const float* __restrict__ B,
    float* __restrict__ C, const float* __restrict__ bias,
    int M, int N, int K)
{
    __shared__ uint32_t As[GBM * SST];
    __shared__ uint32_t Bs[GBN * SST];
    int tid = threadIdx.x;
    int lane = tid & 31;
    int wid = tid >> 5;
    int warp_m = (wid >> 2) * 64;       // 0 / 64
    int warp_n = (wid & 3) * 32;        // 0,32,64,96
    int m0 = blockIdx.y * GBM;
    int n0 = blockIdx.x * GBN;
    int qm = lane >> 2;                 // 0..7
    int qk = lane & 3;                  // 0..3

    float acc[4][4][4];
#pragma unroll
    for (int mt = 0; mt < 4; mt++)
#pragma unroll
        for (int nt = 0; nt < 4; nt++)
#pragma unroll
            for (int r = 0; r < 4; r++) acc[mt][nt][r] = 0.f;

    for (int k0 = 0; k0 < K; k0 += GBK) {
        // stage A and B tiles (128x16 each) as tf32, 2 float4 per thread per tile
#pragma unroll
        for (int it = 0; it < 2; it++) {
            int idx = tid + it * 256;       // 0..511
            int r = idx >> 2;               // 0..127
            int c4 = (idx & 3) << 2;        // 0,4,8,12
            int gm = m0 + r;
            float4 v = make_float4(0.f, 0.f, 0.f, 0.f);
            if (gm < M) v = *(const float4*)(A + (size_t)gm * K + k0 + c4);
            uint32_t* ap = As + r * SST + c4;
            ap[0] = f2tf32(v.x); ap[1] = f2tf32(v.y); ap[2] = f2tf32(v.z); ap[3] = f2tf32(v.w);
            int gn = n0 + r;
            float4 w = make_float4(0.f, 0.f, 0.f, 0.f);
            if (gn < N) w = *(const float4*)(B + (size_t)gn * K + k0 + c4);
            uint32_t* bp = Bs + r * SST + c4;
            bp[0] = f2tf32(w.x); bp[1] = f2tf32(w.y); bp[2] = f2tf32(w.z); bp[3] = f2tf32(w.w);
        }
        __syncthreads();
#pragma unroll
        for (int ks = 0; ks < 2; ks++) {
            int kb = ks * 8;
            uint32_t af[4][4];
#pragma unroll
            for (int mt = 0; mt < 4; mt++) {
                int rb = warp_m + mt * 16 + qm;
                af[mt][0] = As[rb * SST + kb + qk];
                af[mt][1] = As[(rb + 8) * SST + kb + qk];
                af[mt][2] = As[rb * SST + kb + qk + 4];
                af[mt][3] = As[(rb + 8) * SST + kb + qk + 4];
            }
            uint32_t bf[4][2];
#pragma unroll
            for (int nt = 0; nt < 4; nt++) {
                int nb = warp_n + nt * 8 + qm;
                bf[nt][0] = Bs[nb * SST + kb + qk];
                bf[nt][1] = Bs[nb * SST + kb + qk + 4];
            }
#pragma unroll
            for (int mt = 0; mt < 4; mt++)
#pragma unroll
                for (int nt = 0; nt < 4; nt++)
                    mma_tf32(acc[mt][nt], af[mt], bf[nt]);
        }
        __syncthreads();
    }

#pragma unroll
    for (int mt = 0; mt < 4; mt++) {
#pragma unroll
        for (int nt = 0; nt < 4; nt++) {
            int gm = m0 + warp_m + mt * 16 + qm;
            int gn = n0 + warp_n + nt * 8 + 2 * qk;
            if (gn + 1 < N || gn < N) {
                float b0 = bias ? bias[gn] : 0.f;
                float b1 = bias ? bias[gn + 1] : 0.f;
                if (gm < M) {
                    C[(size_t)gm * N + gn]     = acc[mt][nt][0] + b0;
                    C[(size_t)gm * N + gn + 1] = acc[mt][nt][1] + b1;
                }
                if (gm + 8 < M) {
                    C[(size_t)(gm + 8) * N + gn]     = acc[mt][nt][2] + b0;
                    C[(size_t)(gm + 8) * N + gn + 1] = acc[mt][nt][3] + b1;
                }
            }
        }
    }
}

// ---------------- attention logits from xp (layers 1,2; per-head dim d=32) ---
__global__ void k_al(const float* __restrict__ xp, const float* __restrict__ as_,
                     const float* __restrict__ ad_, int d)
{
    int n = blockIdx.x;
    int w = threadIdx.x >> 5, lane = threadIdx.x & 31;
    const float* row = xp + (size_t)n * (HEADS * d) + w * d;
    float s1 = 0.f, s2 = 0.f;
    for (int i = lane; i < d; i += 32) {
        float v = row[i];
        s1 += v * as_[w * d + i];
        s2 += v * ad_[w * d + i];
    }
#pragma unroll
    for (int o = 16; o; o >>= 1) {
        s1 += __shfl_down_sync(0xffffffffu, s1, o);
        s2 += __shfl_down_sync(0xffffffffu, s2, o);
    }
    if (lane == 0) {
        g_als[n * HEADS + w] = s1;
        g_ald[n * HEADS + w] = s2;
    }
}

// ---------------- layer-3: fold attention vectors into input space -----------
// wts[h,k] = sum_d as3[h,d] * W3[h*256+d, k]   (k < 256), same for wtd
__global__ void k_fold3(const float* __restrict__ W3, const float* __restrict__ as3,
                        const float* __restrict__ ad3)
{
    int idx = blockIdx.x * blockDim.x + threadIdx.x;  // 2048 outputs
    if (idx >= HEADS * 256) return;
    int h = idx >> 8, k = idx & 255;
    float s1 = 0.f, s2 = 0.f;
    for (int d = 0; d < 256; d++) {
        float w = W3[(size_t)(h * 256 + d) * 256 + k];
        s1 += as3[h * 256 + d] * w;
        s2 += ad3[h * 256 + d] * w;
    }
    g_wts[idx] = s1;
    g_wtd[idx] = s2;
}

// Wm[j, h*256+k] = 0.125 * W3[h*256+j, k]
__global__ void k_wm(const float* __restrict__ W3) {
    int idx = blockIdx.x * blockDim.x + threadIdx.x;  // 256*2048
    if (idx >= 256 * 2048) return;
    int j = idx >> 11;
    int rem = idx & 2047;
    int h = rem >> 8, k = rem & 255;
    g_Wm[idx] = 0.125f * W3[(size_t)(h * 256 + j) * 256 + k];
}

// al3 directly from h: al[n,h] = h[n,:] . wt[h,:]
__global__ void k_al3(const float* __restrict__ h) {
    int n = blockIdx.x;
    int w = threadIdx.x >> 5, lane = threadIdx.x & 31;
    const float* row = h + (size_t)n * 256;
    float s1 = 0.f, s2 = 0.f;
    for (int i = lane; i < 256; i += 32) {
        float v = row[i];
        s1 += v * g_wts[w * 256 + i];
        s2 += v * g_wtd[w * 256 + i];
    }
#pragma unroll
    for (int o = 16; o; o >>= 1) {
        s1 += __shfl_down_sync(0xffffffffu, s1, o);
        s2 += __shfl_down_sync(0xffffffffu, s2, o);
    }
    if (lane == 0) {
        g_als[n * HEADS + w] = s1;
        g_ald[n * HEADS + w] = s2;
    }
}

// ---------------- edge softmax (per dst node, online) ------------------------
__global__ void k_softmax() {
    int n = blockIdx.x * (blockDim.x >> 5) + (threadIdx.x >> 5);
    if (n >= N_NODES) return;
    int lane = threadIdx.x & 31;
    if (lane >= HEADS) return;
    int lo = g_rowptr[n], hi = g_rowptr[n + 1];
    float adh = g_ald[n * HEADS + lane];
    float eself = leakyf(g_als[n * HEADS + lane] + adh);
    float m = eself, den = 1.f;
    for (int p = lo; p < hi; p++) {
        int s = g_csrc[p];
        float e = leakyf(g_als[s * HEADS + lane] + adh);
        if (e > m) { den = den * __expf(m - e) + 1.f; m = e; }
        else       { den += __expf(e - m); }
    }
    float inv = 1.f / den;
    g_aself[n * HEADS + lane] = __expf(eself - m) * inv;
    for (int p = lo; p < hi; p++) {
        int s = g_csrc[p];
        float e = leakyf(g_als[s * HEADS + lane] + adh);
        g_alpha[(size_t)p * HEADS + lane] = __expf(e - m) * inv;
    }
}

// ---------------- aggregation, d=32 concat (+bias, +ELU) ---------------------
__global__ void k_agg32(const float* __restrict__ xp, const float* __restrict__ bias,
                        float* __restrict__ out)
{
    int n = blockIdx.x * (blockDim.x >> 5) + (threadIdx.x >> 5);
    if (n >= N_NODES) return;
    int lane = threadIdx.x & 31;
    int lo = g_rowptr[n], hi = g_rowptr[n + 1];
    float acc[HEADS];
    {
        float av = (lane < HEADS) ? g_aself[n * HEADS + lane] : 0.f;
        const float* row = xp + (size_t)n * 256;
#pragma unroll
        for (int k = 0; k < HEADS; k++)
            acc[k] = __shfl_sync(0xffffffffu, av, k) * row[k * 32 + lane];
    }
    for (int p = lo; p < hi; p++) {
        int s = g_csrc[p];
        float av = (lane < HEADS) ? g_alpha[(size_t)p * HEADS + lane] : 0.f;
        const float* row = xp + (size_t)s * 256;
#pragma unroll
        for (int k = 0; k < HEADS; k++)
            acc[k] += __shfl_sync(0xffffffffu, av, k) * row[k * 32 + lane];
    }
#pragma unroll
    for (int k = 0; k < HEADS; k++) {
        float v = acc[k] + bias[k * 32 + lane];
        out[(size_t)n * 256 + k * 32 + lane] = eluf(v);
    }
}

// ---------------- layer-3 per-head aggregation of raw h ----------------------
// agg[n, h*256+t] = aself[n,h]*h[n,t] + sum_p alpha[p,h]*h[src_p, t]
__global__ void k_aggH(const float* __restrict__ h, float* __restrict__ agg)
{
    int n = blockIdx.x;
    int t = threadIdx.x;   // 256
    __shared__ float a_sm[32][HEADS];
    __shared__ int s_sm[32];
    int lo = g_rowptr[n], hi = g_rowptr[n + 1];
    float acc[HEADS];
    {
        float hv = h[(size_t)n * 256 + t];
#pragma unroll
        for (int k = 0; k < HEADS; k++)
            acc[k] = g_aself[n * HEADS + k] * hv;
    }
    for (int p0 = lo; p0 < hi; p0 += 32) {
        int cnt = min(32, hi - p0);
        __syncthreads();
        if (t < cnt) s_sm[t] = g_csrc[p0 + t];
        if (t < cnt * HEADS) a_sm[t >> 3][t & 7] = g_alpha[(size_t)p0 * HEADS + t];
        __syncthreads();
        for (int j = 0; j < cnt; j++) {
            float hv = h[(size_t)s_sm[j] * 256 + t];
#pragma unroll
            for (int k = 0; k < HEADS; k++)
                acc[k] += a_sm[j][k] * hv;
        }
    }
#pragma unroll
    for (int k = 0; k < HEADS; k++)
        agg[(size_t)n * 2048 + k * 256 + t] = acc[k];
}

// ---------------- global mean pool (batch is sorted) -------------------------
__device__ __forceinline__ int lower_bound_batch(const int* b, int val) {
    int lo = 0, hi = N_NODES;
    while (lo < hi) {
        int mid = (lo + hi) >> 1;
        if (b[mid] < val) lo = mid + 1; else hi = mid;
    }
    return lo;
}
__global__ void k_pool(const float* __restrict__ h, const int* __restrict__ batch) {
    int g = blockIdx.x;
    int t = threadIdx.x;  // 256
    int lo = lower_bound_batch(batch, g);
    int hi = lower_bound_batch(batch, g + 1);
    float s = 0.f;
    for (int n = lo; n < hi; n++) s += h[(size_t)n * 256 + t];
    float c = (float)max(hi - lo, 1);
    g_gmean[g * 256 + t] = s / c;
}

// ---------------- classifier MLP ---------------------------------------------
__global__ void k_classifier(const float* __restrict__ Wc1, const float* __restrict__ bc1,
                             const float* __restrict__ Wc2, const float* __restrict__ bc2,
                             float* __restrict__ out)
{
    int g = blockIdx.x;
    int t = threadIdx.x;  // 128
    __shared__ float z[128];
    const float* gr = g_gmean + g * 256;
    float s = bc1[t];
    for (int k = 0; k < 256; k++) s += gr[k] * Wc1[t * 256 + k];
    z[t] = eluf(s);
    __syncthreads();
    if (t < 2) {
        float o = bc2[t];
        for (int j = 0; j < 128; j++) o += z[j] * Wc2[t * 128 + j];
        out[g * 2 + t] = o;
    }
}

// ---------------- launch -----------------------------------------------------
extern "C" void kernel_launch(void* const* d_in, const int* in_sizes, int n_in,
                              void* d_out, int out_size)
{
    const float* x      = (const float*)d_in[0];
    const int*   eidx   = (const int*)d_in[1];
    const int*   batch  = (const int*)d_in[2];
    const float* W1  = (const float*)d_in[3];
    const float* as1 = (const float*)d_in[4];
    const float* ad1 = (const float*)d_in[5];
    const float* b1  = (const float*)d_in[6];
    const float* W2  = (const float*)d_in[7];
    const float* as2 = (const float*)d_in[8];
    const float* ad2 = (const float*)d_in[9];
    const float* b2  = (const float*)d_in[10];
    const float* W3  = (const float*)d_in[11];
    const float* as3 = (const float*)d_in[12];
    const float* ad3 = (const float*)d_in[13];
    const float* b3  = (const float*)d_in[14];
    const float* Wc1 = (const float*)d_in[15];
    const float* bc1 = (const float*)d_in[16];
    const float* Wc2 = (const float*)d_in[17];
    const float* bc2 = (const float*)d_in[18];
    float* out = (float*)d_out;

    const int* src = eidx;
    const int* dst = eidx + N_EDGES;

    float* xp = nullptr; cudaGetSymbolAddress((void**)&xp, g_xp);
    float* h  = nullptr; cudaGetSymbolAddress((void**)&h,  g_h);
    float* Wm = nullptr; cudaGetSymbolAddress((void**)&Wm, g_Wm);

    // CSR build (dst-indexed), reused by all 3 layers
    k_zero_deg<<<(N_NODES + 255) / 256, 256>>>();
    k_hist<<<(N_EDGES + 255) / 256, 256>>>(dst);
    k_scan<<<1, 1024>>>();
    k_scatter<<<(N_EDGES + 255) / 256, 256>>>(src, dst);

    // layer-3 weight preprocessing (independent of graph data; cheap)
    k_fold3<<<(2048 + 127) / 128, 128>>>(W3, as3, ad3);
    k_wm<<<(256 * 2048 + 255) / 256, 256>>>(W3);

    dim3 gmm256(256 / GBN, (N_NODES + GBM - 1) / GBM);
    int nwb = (N_NODES + 7) / 8;

    // ---- layer 1: GATConv(32 -> 8x32, concat) + ELU
    k_mma_nt<<<gmm256, 256>>>(x, W1, xp, nullptr, N_NODES, 256, 32);
    k_al<<<N_NODES, 256>>>(xp, as1, ad1, 32);
    k_softmax<<<nwb, 256>>>();
    k_agg32<<<nwb, 256>>>(xp, b1, h);

    // ---- layer 2: GATConv(256 -> 8x32, concat) + ELU
    k_mma_nt<<<gmm256, 256>>>(h, W2, xp, nullptr, N_NODES, 256, 256);
    k_al<<<N_NODES, 256>>>(xp, as2, ad2, 32);
    k_softmax<<<nwb, 256>>>();
    k_agg32<<<nwb, 256>>>(xp, b2, h);

    // ---- layer 3: GATConv(256 -> 8x256, head-mean), restructured:
    //   al from folded vectors; per-head aggregation of h; then one dense GEMM
    k_al3<<<N_NODES, 256>>>(h);
    k_softmax<<<nwb, 256>>>();
    k_aggH<<<N_NODES, 256>>>(h, xp);                       // xp <- agg [50000, 2048]
    k_mma_nt<<<gmm256, 256>>>(xp, Wm, h, b3, N_NODES, 256, 2048);  // h <- out [50000, 256]

    // ---- pool + classifier
    k_pool<<<N_GRAPHS, 256>>>(h, batch);
    k_classifier<<<N_GRAPHS, 128>>>(Wc1, bc1, Wc2, bc2, out);
}

// round 3
// speedup vs baseline: 2.7650x; 1.3072x over previous
#include <cuda_runtime.h>
#include <cuda_bf16.h>
#include <cstdint>

#define N_NODES 50000
#define N_EDGES 800000
#define N_GRAPHS 64
#define HEADS 8
#define NEG_SLOPE 0.2f

// ---------------- scratch (device globals; no allocations allowed) ----------
static __device__ float g_xp[(size_t)N_NODES * 2048];   // projected feats / layer-3 per-head agg (tf32)
static __device__ float g_h[(size_t)N_NODES * 256];     // inter-layer node features (fp32)
static __device__ float g_ht[(size_t)N_NODES * 256];    // tf32-rounded copy of h (GEMM input)
static __device__ float g_xt[(size_t)N_NODES * 32];     // tf32-rounded x
static __device__ float g_w1t[256 * 32];
static __device__ float g_w2t[256 * 256];
static __device__ float g_als[N_NODES * HEADS];
static __device__ float g_ald[N_NODES * HEADS];
static __device__ float g_alpha[(size_t)N_EDGES * HEADS];  // raw leaky logits e
static __device__ float g_aself[N_NODES * HEADS];          // normalized self weight
static __device__ float g_mx[N_NODES * HEADS];
static __device__ float g_inv[N_NODES * HEADS];
static __device__ int   g_deg[N_NODES];
static __device__ int   g_rowptr[N_NODES + 1];
static __device__ int   g_cursor[N_NODES];
static __device__ int   g_csrc[N_EDGES];
static __device__ float g_gmean[N_GRAPHS * 256];
static __device__ float g_wts[HEADS * 256];
static __device__ float g_wtd[HEADS * 256];
static __device__ float g_Wm[256 * 2048];               // rearranged W3 (mean folded, tf32)

__device__ __forceinline__ float leakyf(float x) { return x > 0.f ? x : NEG_SLOPE * x; }
__device__ __forceinline__ float eluf(float x)   { return x > 0.f ? x : (__expf(x) - 1.f); }

__device__ __forceinline__ uint32_t f2tf32(float x) {
    uint32_t r; asm("cvt.rna.tf32.f32 %0, %1;" : "=r"(r) : "f"(x)); return r;
}
__device__ __forceinline__ float roundtf(float x) { return __uint_as_float(f2tf32(x)); }

__device__ __forceinline__ void mma_tf32(float* c, const uint32_t* a, const uint32_t* b) {
    asm volatile(
        "mma.sync.aligned.m16n8k8.row.col.f32.tf32.tf32.f32 "
        "{%0,%1,%2,%3}, {%4,%5,%6,%7}, {%8,%9}, {%0,%1,%2,%3};\n"
        : "+f"(c[0]), "+f"(c[1]), "+f"(c[2]), "+f"(c[3])
        : "r"(a[0]), "r"(a[1]), "r"(a[2]), "r"(a[3]), "r"(b[0]), "r"(b[1]));
}
__device__ __forceinline__ void cp16(uint32_t sa, const float* g, uint32_t sz) {
    asm volatile("cp.async.cg.shared.global [%0], [%1], 16, %2;\n" :: "r"(sa), "l"(g), "r"(sz));
}

// ---------------- elementwise tf32 rounding ----------------------------------
__global__ void k_round(const float* __restrict__ src, float* __restrict__ dst, int n) {
    int i = blockIdx.x * blockDim.x + threadIdx.x;
    if (i < n) dst[i] = roundtf(src[i]);
}

// ---------------- CSR build --------------------------------------------------
__global__ void k_zero_deg() {
    int i = blockIdx.x * blockDim.x + threadIdx.x;
    if (i < N_NODES) g_deg[i] = 0;
}
__global__ void k_hist(const int* __restrict__ dst) {
    int e = blockIdx.x * blockDim.x + threadIdx.x;
    if (e < N_EDGES) atomicAdd(&g_deg[dst[e]], 1);
}
__global__ void k_scan() {   // single block, 1024 threads, shuffle scan
    __shared__ int wsum[32];
    __shared__ int carry_s;
    int t = threadIdx.x, lane = t & 31, w = t >> 5;
    if (t == 0) carry_s = 0;
    __syncthreads();
    for (int base = 0; base < N_NODES; base += 1024) {
        int i = base + t;
        int v = (i < N_NODES) ? g_deg[i] : 0;
        int x = v;
#pragma unroll
        for (int off = 1; off < 32; off <<= 1) {
            int y = __shfl_up_sync(0xffffffffu, x, off);
            if (lane >= off) x += y;
        }
        if (lane == 31) wsum[w] = x;
        __syncthreads();
        if (w == 0) {
            int s = wsum[lane];
#pragma unroll
            for (int off = 1; off < 32; off <<= 1) {
                int y = __shfl_up_sync(0xffffffffu, s, off);
                if (lane >= off) s += y;
            }
            wsum[lane] = s;
        }
        __syncthreads();
        int c = carry_s;
        int incl = x + ((w > 0) ? wsum[w - 1] : 0);
        if (i < N_NODES) { g_rowptr[i] = c + incl - v; g_cursor[i] = c + incl - v; }
        __syncthreads();
        if (t == 1023) carry_s = c + incl;
        __syncthreads();
    }
    if (t == 0) g_rowptr[N_NODES] = N_EDGES;
}
__global__ void k_scatter(const int* __restrict__ src, const int* __restrict__ dst) {
    int e = blockIdx.x * blockDim.x + threadIdx.x;
    if (e < N_EDGES) {
        int d = dst[e];
        int pos = atomicAdd(&g_cursor[d], 1);
        g_csrc[pos] = src[e];
    }
}

// ---------------- pipelined tf32 GEMM: C[M,256] = A[M,K] * B[256,K]^T (+bias)
// inputs pre-rounded to tf32. 128x256 block tile, BK=32, 3-stage cp.async.
#define GSM_A (128 * 32)
#define GSM_B (256 * 32)
#define GSM_BYTES (3 * (GSM_A + GSM_B) * 4)

__global__ __launch_bounds__(256, 1) void k_mma2(
    const float* __restrict__ A, const float* __restrict__ B,
    float* __restrict__ C, const float* __restrict__ bias,
    int M, int K)
{
    extern __shared__ float smem[];
    float* As = smem;                 // 3 stages of 128x32
    float* Bs = smem + 3 * GSM_A;     // 3 stages of 256x32
    uint32_t As_u = (uint32_t)__cvta_generic_to_shared(As);
    uint32_t Bs_u = (uint32_t)__cvta_generic_to_shared(Bs);

    int tid = threadIdx.x;
    int lane = tid & 31, wid = tid >> 5;
    int qm = lane >> 2, qk = lane & 3;
    int wm = (wid >> 2) * 64;     // 0 / 64
    int wn = (wid & 3) * 64;      // 0..192
    int m0 = blockIdx.x * 128;

    float acc[4][8][4];
#pragma unroll
    for (int mt = 0; mt < 4; mt++)
#pragma unroll
        for (int nt = 0; nt < 8; nt++)
#pragma unroll
            for (int r = 0; r < 4; r++) acc[mt][nt][r] = 0.f;

    auto stage = [&](int s, int k0) {
#pragma unroll
        for (int i = 0; i < 4; i++) {            // A: 128 rows x 8 chunks
            int idx = tid + i * 256;
            int r = idx >> 3, cc = idx & 7;
            int gm = m0 + r;
            const float* srcp = A + (size_t)(gm < M ? gm : (M - 1)) * K + k0 + cc * 4;
            uint32_t dstp = As_u + (uint32_t)(s * GSM_A + r * 32 + ((cc ^ (r & 7)) << 2)) * 4u;
            cp16(dstp, srcp, (gm < M) ? 16u : 0u);
        }
#pragma unroll
        for (int i = 0; i < 8; i++) {            // B: 256 rows x 8 chunks
            int idx = tid + i * 256;
            int r = idx >> 3, cc = idx & 7;
            const float* srcp = B + (size_t)r * K + k0 + cc * 4;
            uint32_t dstp = Bs_u + (uint32_t)(s * GSM_B + r * 32 + ((cc ^ (r & 7)) << 2)) * 4u;
            cp16(dstp, srcp, 16u);
        }
    };

    int niter = K >> 5;
    stage(0, 0);
    asm volatile("cp.async.commit_group;");
    if (K > 32) stage(1, 32);
    asm volatile("cp.async.commit_group;");

    for (int i = 0; i < niter; i++) {
        asm volatile("cp.async.wait_group 1;");
        __syncthreads();
        int knext = (i + 2) << 5;
        if (knext < K) stage((i + 2) % 3, knext);
        asm volatile("cp.async.commit_group;");

        const float* Ab = As + (i % 3) * GSM_A;
        const float* Bb = Bs + (i % 3) * GSM_B;
#pragma unroll
        for (int ks = 0; ks < 4; ks++) {
            int lo  = (((2 * ks)     ^ qm) << 2) + qk;
            int hi2 = (((2 * ks + 1) ^ qm) << 2) + qk;
            uint32_t af[4][4], bf[8][2];
#pragma unroll
            for (int mt = 0; mt < 4; mt++) {
                int rm = wm + mt * 16 + qm;
                af[mt][0] = __float_as_uint(Ab[rm * 32 + lo]);
                af[mt][1] = __float_as_uint(Ab[(rm + 8) * 32 + lo]);
                af[mt][2] = __float_as_uint(Ab[rm * 32 + hi2]);
                af[mt][3] = __float_as_uint(Ab[(rm + 8) * 32 + hi2]);
            }
#pragma unroll
            for (int nt = 0; nt < 8; nt++) {
                int rn = wn + nt * 8 + qm;
                bf[nt][0] = __float_as_uint(Bb[rn * 32 + lo]);
                bf[nt][1] = __float_as_uint(Bb[rn * 32 + hi2]);
            }
#pragma unroll
            for (int mt = 0; mt < 4; mt++)
#pragma unroll
                for (int nt = 0; nt < 8; nt++)
                    mma_tf32(acc[mt][nt], af[mt], bf[nt]);
        }
        __syncthreads();
    }

#pragma unroll
    for (int mt = 0; mt < 4; mt++) {
#pragma unroll
        for (int nt = 0; nt < 8; nt++) {
            int gm = m0 + wm + mt * 16 + qm;
            int gn = wn + nt * 8 + 2 * qk;
            float b0 = bias ? bias[gn] : 0.f;
            float b1 = bias ? bias[gn + 1] : 0.f;
            if (gm < M) {
                C[(size_t)gm * 256 + gn]     = acc[mt][nt][0] + b0;
                C[(size_t)gm * 256 + gn + 1] = acc[mt][nt][1] + b1;
            }
            if (gm + 8 < M) {
                C[(size_t)(gm + 8) * 256 + gn]     = acc[mt][nt][2] + b0;
                C[(size_t)(gm + 8) * 256 + gn + 1] = acc[mt][nt][3] + b1;
            }
        }
    }
}

// ---------------- attention logits from xp (layers 1,2; per-head dim 32) -----
__global__ void k_al(const float* __restrict__ xp, const float* __restrict__ as_,
                     const float* __restrict__ ad_)
{
    int n = blockIdx.x;
    int w = threadIdx.x >> 5, lane = threadIdx.x & 31;
    const float* row = xp + (size_t)n * 256 + w * 32;
    float v = row[lane];
    float s1 = v * as_[w * 32 + lane];
    float s2 = v * ad_[w * 32 + lane];
#pragma unroll
    for (int o = 16; o; o >>= 1) {
        s1 += __shfl_down_sync(0xffffffffu, s1, o);
        s2 += __shfl_down_sync(0xffffffffu, s2, o);
    }
    if (lane == 0) {
        g_als[n * HEADS + w] = s1;
        g_ald[n * HEADS + w] = s2;
    }
}

// ---------------- layer-3 folded attention vectors ---------------------------
__global__ void k_fold3(const float* __restrict__ W3, const float* __restrict__ as3,
                        const float* __restrict__ ad3)
{
    int idx = blockIdx.x * blockDim.x + threadIdx.x;
    if (idx >= HEADS * 256) return;
    int h = idx >> 8, k = idx & 255;
    float s1 = 0.f, s2 = 0.f;
    for (int d = 0; d < 256; d++) {
        float w = W3[(size_t)(h * 256 + d) * 256 + k];
        s1 += as3[h * 256 + d] * w;
        s2 += ad3[h * 256 + d] * w;
    }
    g_wts[idx] = s1;
    g_wtd[idx] = s2;
}

__global__ void k_wm(const float* __restrict__ W3) {
    int idx = blockIdx.x * blockDim.x + threadIdx.x;
    if (idx >= 256 * 2048) return;
    int j = idx >> 11;
    int rem = idx & 2047;
    int h = rem >> 8, k = rem & 255;
    g_Wm[idx] = roundtf(0.125f * W3[(size_t)(h * 256 + j) * 256 + k]);
}

__global__ void k_al3(const float* __restrict__ h) {
    int n = blockIdx.x;
    int w = threadIdx.x >> 5, lane = threadIdx.x & 31;
    const float* row = h + (size_t)n * 256;
    float s1 = 0.f, s2 = 0.f;
    for (int i = lane; i < 256; i += 32) {
        float v = row[i];
        s1 += v * g_wts[w * 256 + i];
        s2 += v * g_wtd[w * 256 + i];
    }
#pragma unroll
    for (int o = 16; o; o >>= 1) {
        s1 += __shfl_down_sync(0xffffffffu, s1, o);
        s2 += __shfl_down_sync(0xffffffffu, s2, o);
    }
    if (lane == 0) {
        g_als[n * HEADS + w] = s1;
        g_ald[n * HEADS + w] = s2;
    }
}

// ---------------- edge softmax: single gather pass, store raw logits ---------
// warp per node: lane = j*8 + head, 4 edges per iteration
__global__ void k_softmax() {
    int n = blockIdx.x * (blockDim.x >> 5) + (threadIdx.x >> 5);
    if (n >= N_NODES) return;
    int lane = threadIdx.x & 31;
    int j = lane >> 3, hd = lane & 7;
    int lo = g_rowptr[n], hi = g_rowptr[n + 1];
    float adh = g_ald[n * HEADS + hd];
    float m = -INFINITY, den = 0.f;
    for (int p = lo + j; p < hi; p += 4) {
        int s = g_csrc[p];
        float e = leakyf(g_als[s * HEADS + hd] + adh);
        g_alpha[(size_t)p * HEADS + hd] = e;
        if (e > m) { den = den * __expf(m - e) + 1.f; m = e; }
        else       { den += __expf(e - m); }
    }
#pragma unroll
    for (int off = 8; off <= 16; off <<= 1) {
        float mo = __shfl_xor_sync(0xffffffffu, m, off);
        float dn = __shfl_xor_sync(0xffffffffu, den, off);
        float mn = fmaxf(m, mo);
        float t1 = (m  == -INFINITY) ? 0.f : den * __expf(m - mn);
        float t2 = (mo == -INFINITY) ? 0.f : dn  * __expf(mo - mn);
        den = t1 + t2; m = mn;
    }
    float eself = leakyf(g_als[n * HEADS + hd] + adh);
    float mn = fmaxf(m, eself);
    den = ((m == -INFINITY) ? 0.f : den * __expf(m - mn)) + __expf(eself - mn);
    m = mn;
    float inv = 1.f / den;
    if (lane < 8) {
        g_aself[n * HEADS + hd] = __expf(eself - m) * inv;
        g_mx[n * HEADS + hd] = m;
        g_inv[n * HEADS + hd] = inv;
    }
}

// ---------------- aggregation, d=32 concat (+bias, +ELU) ---------------------
__global__ void k_agg32(const float* __restrict__ xp, const float* __restrict__ bias,
                        float* __restrict__ out, float* __restrict__ out_t32)
{
    int n = blockIdx.x * (blockDim.x >> 5) + (threadIdx.x >> 5);
    if (n >= N_NODES) return;
    int lane = threadIdx.x & 31;
    int lo = g_rowptr[n], hi = g_rowptr[n + 1];
    float mh = 0.f, invh = 0.f;
    if (lane < 8) { mh = g_mx[n * HEADS + lane]; invh = g_inv[n * HEADS + lane]; }
    float acc[HEADS];
    {
        float av = (lane < 8) ? g_aself[n * HEADS + lane] : 0.f;
        const float* row = xp + (size_t)n * 256;
#pragma unroll
        for (int k = 0; k < HEADS; k++)
            acc[k] = __shfl_sync(0xffffffffu, av, k) * row[k * 32 + lane];
    }
    for (int p = lo; p < hi; p++) {
        int s = g_csrc[p];
        float av = 0.f;
        if (lane < 8) {
            float e = g_alpha[(size_t)p * HEADS + lane];
            av = __expf(e - mh) * invh;
        }
        const float* row = xp + (size_t)s * 256;
#pragma unroll
        for (int k = 0; k < HEADS; k++)
            acc[k] += __shfl_sync(0xffffffffu, av, k) * row[k * 32 + lane];
    }
#pragma unroll
    for (int k = 0; k < HEADS; k++) {
        float v = eluf(acc[k] + bias[k * 32 + lane]);
        out[(size_t)n * 256 + k * 32 + lane] = v;
        if (out_t32) out_t32[(size_t)n * 256 + k * 32 + lane] = roundtf(v);
    }
}

// ---------------- layer-3 per-head aggregation of raw h (tf32 output) --------
__global__ void k_aggH(const float* __restrict__ h, float* __restrict__ agg)
{
    int n = blockIdx.x;
    int t = threadIdx.x;   // 256
    __shared__ float a_sm[32][HEADS];
    __shared__ int s_sm[32];
    __shared__ float m_s[HEADS], i_s[HEADS];
    int lo = g_rowptr[n], hi = g_rowptr[n + 1];
    if (t < 8) { m_s[t] = g_mx[n * HEADS + t]; i_s[t] = g_inv[n * HEADS + t]; }
    __syncthreads();
    float acc[HEADS];
    {
        float hv = h[(size_t)n * 256 + t];
#pragma unroll
        for (int k = 0; k < HEADS; k++)
            acc[k] = g_aself[n * HEADS + k] * hv;
    }
    for (int p0 = lo; p0 < hi; p0 += 32) {
        int cnt = min(32, hi - p0);
        __syncthreads();
        if (t < cnt) s_sm[t] = g_csrc[p0 + t];
        if (t < cnt * HEADS) {
            float e = g_alpha[(size_t)p0 * HEADS + t];
            a_sm[t >> 3][t & 7] = __expf(e - m_s[t & 7]) * i_s[t & 7];
        }
        __syncthreads();
        for (int jj = 0; jj < cnt; jj++) {
            float hv = h[(size_t)s_sm[jj] * 256 + t];
#pragma unroll
            for (int k = 0; k < HEADS; k++)
                acc[k] += a_sm[jj][k] * hv;
        }
    }
#pragma unroll
    for (int k = 0; k < HEADS; k++)
        agg[(size_t)n * 2048 + k * 256 + t] = roundtf(acc[k]);
}

// ---------------- global mean pool (batch is sorted) -------------------------
__device__ __forceinline__ int lower_bound_batch(const int* b, int val) {
    int lo = 0, hi = N_NODES;
    while (lo < hi) {
        int mid = (lo + hi) >> 1;
        if (b[mid] < val) lo = mid + 1; else hi = mid;
    }
    return lo;
}
__global__ void k_pool(const float* __restrict__ h, const int* __restrict__ batch) {
    int g = blockIdx.x;
    int t = threadIdx.x;  // 256
    int lo = lower_bound_batch(batch, g);
    int hi = lower_bound_batch(batch, g + 1);
    float s = 0.f;
    for (int n = lo; n < hi; n++) s += h[(size_t)n * 256 + t];
    float c = (float)max(hi - lo, 1);
    g_gmean[g * 256 + t] = s / c;
}

// ---------------- classifier MLP ---------------------------------------------
__global__ void k_classifier(const float* __restrict__ Wc1, const float* __restrict__ bc1,
                             const float* __restrict__ Wc2, const float* __restrict__ bc2,
                             float* __restrict__ out)
{
    int g = blockIdx.x;
    int t = threadIdx.x;  // 128
    __shared__ float z[128];
    const float* gr = g_gmean + g * 256;
    float s = bc1[t];
    for (int k = 0; k < 256; k++) s += gr[k] * Wc1[t * 256 + k];
    z[t] = eluf(s);
    __syncthreads();
    if (t < 2) {
        float o = bc2[t];
        for (int jj = 0; jj < 128; jj++) o += z[jj] * Wc2[t * 128 + jj];
        out[g * 2 + t] = o;
    }
}

// ---------------- launch -----------------------------------------------------
extern "C" void kernel_launch(void* const* d_in, const int* in_sizes, int n_in,
                              void* d_out, int out_size)
{
    const float* x      = (const float*)d_in[0];
    const int*   eidx   = (const int*)d_in[1];
    const int*   batch  = (const int*)d_in[2];
    const float* W1  = (const float*)d_in[3];
    const float* as1 = (const float*)d_in[4];
    const float* ad1 = (const float*)d_in[5];
    const float* b1  = (const float*)d_in[6];
    const float* W2  = (const float*)d_in[7];
    const float* as2 = (const float*)d_in[8];
    const float* ad2 = (const float*)d_in[9];
    const float* b2  = (const float*)d_in[10];
    const float* W3  = (const float*)d_in[11];
    const float* as3 = (const float*)d_in[12];
    const float* ad3 = (const float*)d_in[13];
    const float* b3  = (const float*)d_in[14];
    const float* Wc1 = (const float*)d_in[15];
    const float* bc1 = (const float*)d_in[16];
    const float* Wc2 = (const float*)d_in[17];
    const float* bc2 = (const float*)d_in[18];
    float* out = (float*)d_out;

    const int* src = eidx;
    const int* dst = eidx + N_EDGES;

    float* xp = nullptr; cudaGetSymbolAddress((void**)&xp, g_xp);
    float* h  = nullptr; cudaGetSymbolAddress((void**)&h,  g_h);
    float* ht = nullptr; cudaGetSymbolAddress((void**)&ht, g_ht);
    float* xt = nullptr; cudaGetSymbolAddress((void**)&xt, g_xt);
    float* w1t = nullptr; cudaGetSymbolAddress((void**)&w1t, g_w1t);
    float* w2t = nullptr; cudaGetSymbolAddress((void**)&w2t, g_w2t);
    float* Wm = nullptr; cudaGetSymbolAddress((void**)&Wm, g_Wm);

    cudaFuncSetAttribute(k_mma2, cudaFuncAttributeMaxDynamicSharedMemorySize, GSM_BYTES);

    // CSR build (dst-indexed), reused by all 3 layers
    k_zero_deg<<<(N_NODES + 255) / 256, 256>>>();
    k_hist<<<(N_EDGES + 255) / 256, 256>>>(dst);
    k_scan<<<1, 1024>>>();
    k_scatter<<<(N_EDGES + 255) / 256, 256>>>(src, dst);

    // preprocessing: tf32 rounding + layer-3 weight folding
    k_round<<<(N_NODES * 32 + 255) / 256, 256>>>(x, xt, N_NODES * 32);
    k_round<<<(256 * 32 + 255) / 256, 256>>>(W1, w1t, 256 * 32);
    k_round<<<(256 * 256 + 255) / 256, 256>>>(W2, w2t, 256 * 256);
    k_fold3<<<(2048 + 127) / 128, 128>>>(W3, as3, ad3);
    k_wm<<<(256 * 2048 + 255) / 256, 256>>>(W3);

    int gm = (N_NODES + 127) / 128;      // 391 blocks
    int nwb = (N_NODES + 7) / 8;

    // ---- layer 1: GATConv(32 -> 8x32, concat) + ELU
    k_mma2<<<gm, 256, GSM_BYTES>>>(xt, w1t, xp, nullptr, N_NODES, 32);
    k_al<<<N_NODES, 256>>>(xp, as1, ad1);
    k_softmax<<<nwb, 256>>>();
    k_agg32<<<nwb, 256>>>(xp, b1, h, ht);

    // ---- layer 2: GATConv(256 -> 8x32, concat) + ELU
    k_mma2<<<gm, 256, GSM_BYTES>>>(ht, w2t, xp, nullptr, N_NODES, 256);
    k_al<<<N_NODES, 256>>>(xp, as2, ad2);
    k_softmax<<<nwb, 256>>>();
    k_agg32<<<nwb, 256>>>(xp, b2, h, nullptr);

    // ---- layer 3: GATConv(256 -> 8x256, head-mean) restructured
    k_al3<<<N_NODES, 256>>>(h);
    k_softmax<<<nwb, 256>>>();
    k_aggH<<<N_NODES, 256>>>(h, xp);                     // xp <- agg [50000, 2048] (tf32)
    k_mma2<<<gm, 256, GSM_BYTES>>>(xp, Wm, h, b3, N_NODES, 2048);

    // ---- pool + classifier
    k_pool<<<N_GRAPHS, 256>>>(h, batch);
    k_classifier<<<N_GRAPHS, 128>>>(Wc1, bc1, Wc2, bc2, out);
}

// round 5
// speedup vs baseline: 3.2241x; 1.1661x over previous
#include <cuda_runtime.h>
#include <cuda_bf16.h>
#include <cstdint>

#define N_NODES 50000
#define N_EDGES 800000
#define N_GRAPHS 64
#define HEADS 8
#define NEG_SLOPE 0.2f

// ---------------- scratch (device globals; no allocations allowed) ----------
static __device__ float g_xp[(size_t)N_NODES * 256];    // projected features (layers 1,2)
static __device__ float g_h[(size_t)N_NODES * 256];     // inter-layer node features
static __device__ float g_xt[(size_t)N_NODES * 32];     // tf32-rounded x
static __device__ float g_w1t[256 * 32];
static __device__ float g_w2t[256 * 256];
static __device__ float g_als[N_NODES * HEADS];
static __device__ float g_ald[N_NODES * HEADS];
static __device__ float g_alpha[(size_t)N_EDGES * HEADS];  // raw leaky logits e (layer 3)
static __device__ float g_aself[N_NODES * HEADS];
static __device__ float g_mx[N_NODES * HEADS];
static __device__ float g_inv[N_NODES * HEADS];
static __device__ int   g_deg[N_NODES];
static __device__ int   g_rowptr[N_NODES + 1];
static __device__ int   g_cursor[N_NODES];
static __device__ int   g_csrc[N_EDGES];
static __device__ float g_pool[N_GRAPHS * 2048];        // per-graph sum of layer-3 agg
static __device__ float g_gmean[N_GRAPHS * 256];
static __device__ float g_wts[HEADS * 256];
static __device__ float g_wtd[HEADS * 256];

__device__ __forceinline__ float leakyf(float x) { return x > 0.f ? x : NEG_SLOPE * x; }
__device__ __forceinline__ float eluf(float x)   { return x > 0.f ? x : (__expf(x) - 1.f); }

__device__ __forceinline__ uint32_t f2tf32(float x) {
    uint32_t r; asm("cvt.rna.tf32.f32 %0, %1;" : "=r"(r) : "f"(x)); return r;
}
__device__ __forceinline__ float roundtf(float x) { return __uint_as_float(f2tf32(x)); }

__device__ __forceinline__ void mma_tf32(float* c, const uint32_t* a, const uint32_t* b) {
    asm volatile(
        "mma.sync.aligned.m16n8k8.row.col.f32.tf32.tf32.f32 "
        "{%0,%1,%2,%3}, {%4,%5,%6,%7}, {%8,%9}, {%0,%1,%2,%3};\n"
        : "+f"(c[0]), "+f"(c[1]), "+f"(c[2]), "+f"(c[3])
        : "r"(a[0]), "r"(a[1]), "r"(a[2]), "r"(a[3]), "r"(b[0]), "r"(b[1]));
}
__device__ __forceinline__ void cp16(uint32_t sa, const float* g, uint32_t sz) {
    asm volatile("cp.async.cg.shared.global [%0], [%1], 16, %2;\n" :: "r"(sa), "l"(g), "r"(sz));
}

// ---------------- elementwise tf32 rounding ----------------------------------
__global__ void k_round(const float* __restrict__ src, float* __restrict__ dst, int n) {
    int i = blockIdx.x * blockDim.x + threadIdx.x;
    if (i < n) dst[i] = roundtf(src[i]);
}

// ---------------- CSR build --------------------------------------------------
__global__ void k_zero_deg() {
    int i = blockIdx.x * blockDim.x + threadIdx.x;
    if (i < N_NODES) g_deg[i] = 0;
}
__global__ void k_hist(const int* __restrict__ dst) {
    int e = blockIdx.x * blockDim.x + threadIdx.x;
    if (e < N_EDGES) atomicAdd(&g_deg[dst[e]], 1);
}
__global__ void k_scan() {   // single block, 1024 threads, shuffle scan
    __shared__ int wsum[32];
    __shared__ int carry_s;
    int t = threadIdx.x, lane = t & 31, w = t >> 5;
    if (t == 0) carry_s = 0;
    __syncthreads();
    for (int base = 0; base < N_NODES; base += 1024) {
        int i = base + t;
        int v = (i < N_NODES) ? g_deg[i] : 0;
        int x = v;
#pragma unroll
        for (int off = 1; off < 32; off <<= 1) {
            int y = __shfl_up_sync(0xffffffffu, x, off);
            if (lane >= off) x += y;
        }
        if (lane == 31) wsum[w] = x;
        __syncthreads();
        if (w == 0) {
            int s = wsum[lane];
#pragma unroll
            for (int off = 1; off < 32; off <<= 1) {
                int y = __shfl_up_sync(0xffffffffu, s, off);
                if (lane >= off) s += y;
            }
            wsum[lane] = s;
        }
        __syncthreads();
        int c = carry_s;
        int incl = x + ((w > 0) ? wsum[w - 1] : 0);
        if (i < N_NODES) { g_rowptr[i] = c + incl - v; g_cursor[i] = c + incl - v; }
        __syncthreads();
        if (t == 1023) carry_s = c + incl;
        __syncthreads();
    }
    if (t == 0) g_rowptr[N_NODES] = N_EDGES;
}
__global__ void k_scatter(const int* __restrict__ src, const int* __restrict__ dst) {
    int e = blockIdx.x * blockDim.x + threadIdx.x;
    if (e < N_EDGES) {
        int d = dst[e];
        int pos = atomicAdd(&g_cursor[d], 1);
        g_csrc[pos] = src[e];
    }
}

// ---------------- pipelined legacy tf32 GEMM: C[M,256] = A[M,K]*B[256,K]^T ---
#define GSM_A (128 * 32)
#define GSM_B (256 * 32)
#define GSM_BYTES (3 * (GSM_A + GSM_B) * 4)

__global__ __launch_bounds__(256, 1) void k_mma2(
    const float* __restrict__ A, const float* __restrict__ B,
    float* __restrict__ C, const float* __restrict__ bias,
    int M, int K)
{
    extern __shared__ float smem[];
    float* As = smem;
    float* Bs = smem + 3 * GSM_A;
    uint32_t As_u = (uint32_t)__cvta_generic_to_shared(As);
    uint32_t Bs_u = (uint32_t)__cvta_generic_to_shared(Bs);

    int tid = threadIdx.x;
    int lane = tid & 31, wid = tid >> 5;
    int qm = lane >> 2, qk = lane & 3;
    int wm = (wid >> 2) * 64;
    int wn = (wid & 3) * 64;
    int m0 = blockIdx.x * 128;

    float acc[4][8][4];
#pragma unroll
    for (int mt = 0; mt < 4; mt++)
#pragma unroll
        for (int nt = 0; nt < 8; nt++)
#pragma unroll
            for (int r = 0; r < 4; r++) acc[mt][nt][r] = 0.f;

    auto stage = [&](int s, int k0) {
#pragma unroll
        for (int i = 0; i < 4; i++) {
            int idx = tid + i * 256;
            int r = idx >> 3, cc = idx & 7;
            int gm = m0 + r;
            const float* srcp = A + (size_t)(gm < M ? gm : (M - 1)) * K + k0 + cc * 4;
            uint32_t dstp = As_u + (uint32_t)(s * GSM_A + r * 32 + ((cc ^ (r & 7)) << 2)) * 4u;
            cp16(dstp, srcp, (gm < M) ? 16u : 0u);
        }
#pragma unroll
        for (int i = 0; i < 8; i++) {
            int idx = tid + i * 256;
            int r = idx >> 3, cc = idx & 7;
            const float* srcp = B + (size_t)r * K + k0 + cc * 4;
            uint32_t dstp = Bs_u + (uint32_t)(s * GSM_B + r * 32 + ((cc ^ (r & 7)) << 2)) * 4u;
            cp16(dstp, srcp, 16u);
        }
    };

    int niter = K >> 5;
    stage(0, 0);
    asm volatile("cp.async.commit_group;");
    if (K > 32) stage(1, 32);
    asm volatile("cp.async.commit_group;");

    for (int i = 0; i < niter; i++) {
        asm volatile("cp.async.wait_group 1;");
        __syncthreads();
        int knext = (i + 2) << 5;
        if (knext < K) stage((i + 2) % 3, knext);
        asm volatile("cp.async.commit_group;");

        const float* Ab = As + (i % 3) * GSM_A;
        const float* Bb = Bs + (i % 3) * GSM_B;
#pragma unroll
        for (int ks = 0; ks < 4; ks++) {
            int lo  = (((2 * ks)     ^ qm) << 2) + qk;
            int hi2 = (((2 * ks + 1) ^ qm) << 2) + qk;
            uint32_t af[4][4], bf[8][2];
#pragma unroll
            for (int mt = 0; mt < 4; mt++) {
                int rm = wm + mt * 16 + qm;
                af[mt][0] = __float_as_uint(Ab[rm * 32 + lo]);
                af[mt][1] = __float_as_uint(Ab[(rm + 8) * 32 + lo]);
                af[mt][2] = __float_as_uint(Ab[rm * 32 + hi2]);
                af[mt][3] = __float_as_uint(Ab[(rm + 8) * 32 + hi2]);
            }
#pragma unroll
            for (int nt = 0; nt < 8; nt++) {
                int rn = wn + nt * 8 + qm;
                bf[nt][0] = __float_as_uint(Bb[rn * 32 + lo]);
                bf[nt][1] = __float_as_uint(Bb[rn * 32 + hi2]);
            }
#pragma unroll
            for (int mt = 0; mt < 4; mt++)
#pragma unroll
                for (int nt = 0; nt < 8; nt++)
                    mma_tf32(acc[mt][nt], af[mt], bf[nt]);
        }
        __syncthreads();
    }

#pragma unroll
    for (int mt = 0; mt < 4; mt++) {
#pragma unroll
        for (int nt = 0; nt < 8; nt++) {
            int gm = m0 + wm + mt * 16 + qm;
            int gn = wn + nt * 8 + 2 * qk;
            float b0 = bias ? bias[gn] : 0.f;
            float b1 = bias ? bias[gn + 1] : 0.f;
            if (gm < M) {
                C[(size_t)gm * 256 + gn]     = acc[mt][nt][0] + b0;
                C[(size_t)gm * 256 + gn + 1] = acc[mt][nt][1] + b1;
            }
            if (gm + 8 < M) {
                C[(size_t)(gm + 8) * 256 + gn]     = acc[mt][nt][2] + b0;
                C[(size_t)(gm + 8) * 256 + gn + 1] = acc[mt][nt][3] + b1;
            }
        }
    }
}

// ---------------- attention logits from xp (layers 1,2; per-head dim 32) -----
__global__ void k_al(const float* __restrict__ xp, const float* __restrict__ as_,
                     const float* __restrict__ ad_)
{
    int n = blockIdx.x;
    int w = threadIdx.x >> 5, lane = threadIdx.x & 31;
    const float* row = xp + (size_t)n * 256 + w * 32;
    float v = row[lane];
    float s1 = v * as_[w * 32 + lane];
    float s2 = v * ad_[w * 32 + lane];
#pragma unroll
    for (int o = 16; o; o >>= 1) {
        s1 += __shfl_down_sync(0xffffffffu, s1, o);
        s2 += __shfl_down_sync(0xffffffffu, s2, o);
    }
    if (lane == 0) {
        g_als[n * HEADS + w] = s1;
        g_ald[n * HEADS + w] = s2;
    }
}

// ---------------- layer-3 folded attention vectors ---------------------------
__global__ void k_fold3(const float* __restrict__ W3, const float* __restrict__ as3,
                        const float* __restrict__ ad3)
{
    int idx = blockIdx.x * blockDim.x + threadIdx.x;
    if (idx >= HEADS * 256) return;
    int h = idx >> 8, k = idx & 255;
    float s1 = 0.f, s2 = 0.f;
    for (int d = 0; d < 256; d++) {
        float w = W3[(size_t)(h * 256 + d) * 256 + k];
        s1 += as3[h * 256 + d] * w;
        s2 += ad3[h * 256 + d] * w;
    }
    g_wts[idx] = s1;
    g_wtd[idx] = s2;
}

__global__ void k_al3(const float* __restrict__ h) {
    int n = blockIdx.x;
    int w = threadIdx.x >> 5, lane = threadIdx.x & 31;
    const float* row = h + (size_t)n * 256;
    float s1 = 0.f, s2 = 0.f;
    for (int i = lane; i < 256; i += 32) {
        float v = row[i];
        s1 += v * g_wts[w * 256 + i];
        s2 += v * g_wtd[w * 256 + i];
    }
#pragma unroll
    for (int o = 16; o; o >>= 1) {
        s1 += __shfl_down_sync(0xffffffffu, s1, o);
        s2 += __shfl_down_sync(0xffffffffu, s2, o);
    }
    if (lane == 0) {
        g_als[n * HEADS + w] = s1;
        g_ald[n * HEADS + w] = s2;
    }
}

// ---------------- fused softmax + aggregation (layers 1,2) -------------------
// warp per node: pass1 (m, den) with lane=j*8+hd split; pass2 weighted agg.
__global__ void k_gat32(const float* __restrict__ xp, const float* __restrict__ bias,
                        float* __restrict__ out)
{
    int n = blockIdx.x * (blockDim.x >> 5) + (threadIdx.x >> 5);
    if (n >= N_NODES) return;
    int lane = threadIdx.x & 31;
    int j = lane >> 3, hd = lane & 7;
    int lo = g_rowptr[n], hi = g_rowptr[n + 1];
    float adh = g_ald[n * HEADS + hd];

    // pass 1: online max/denominator over edges (4-way edge split per head)
    float m = -INFINITY, den = 0.f;
    for (int p = lo + j; p < hi; p += 4) {
        int s = g_csrc[p];
        float e = leakyf(g_als[s * HEADS + hd] + adh);
        if (e > m) { den = den * __expf(m - e) + 1.f; m = e; }
        else       { den += __expf(e - m); }
    }
#pragma unroll
    for (int off = 8; off <= 16; off <<= 1) {
        float mo = __shfl_xor_sync(0xffffffffu, m, off);
        float dn = __shfl_xor_sync(0xffffffffu, den, off);
        float mn = fmaxf(m, mo);
        float t1 = (m  == -INFINITY) ? 0.f : den * __expf(m - mn);
        float t2 = (mo == -INFINITY) ? 0.f : dn  * __expf(mo - mn);
        den = t1 + t2; m = mn;
    }
    float eself = leakyf(g_als[n * HEADS + hd] + adh);
    float mn = fmaxf(m, eself);
    den = ((m == -INFINITY) ? 0.f : den * __expf(m - mn)) + __expf(eself - mn);
    m = mn;
    float inv = 1.f / den;

    // pass 2: weighted aggregation. lanes 0..7 hold (adh, m, inv) for head=lane.
    float acc[HEADS];
    {
        float av = __expf(eself - m) * inv;   // lanes 0..7 valid
        const float* row = xp + (size_t)n * 256;
#pragma unroll
        for (int k = 0; k < HEADS; k++)
            acc[k] = __shfl_sync(0xffffffffu, av, k) * row[k * 32 + lane];
    }
    for (int p = lo; p < hi; p++) {
        int s = g_csrc[p];
        float av = 0.f;
        if (lane < 8) {
            float e = leakyf(g_als[s * HEADS + lane] + adh);
            av = __expf(e - m) * inv;
        }
        const float* row = xp + (size_t)s * 256;
#pragma unroll
        for (int k = 0; k < HEADS; k++)
            acc[k] += __shfl_sync(0xffffffffu, av, k) * row[k * 32 + lane];
    }
#pragma unroll
    for (int k = 0; k < HEADS; k++) {
        float v = eluf(acc[k] + bias[k * 32 + lane]);
        out[(size_t)n * 256 + k * 32 + lane] = roundtf(v);
    }
}

// ---------------- layer-3 softmax (writes alpha/mx/inv/aself) ----------------
__global__ void k_softmax() {
    int n = blockIdx.x * (blockDim.x >> 5) + (threadIdx.x >> 5);
    if (n >= N_NODES) return;
    int lane = threadIdx.x & 31;
    int j = lane >> 3, hd = lane & 7;
    int lo = g_rowptr[n], hi = g_rowptr[n + 1];
    float adh = g_ald[n * HEADS + hd];
    float m = -INFINITY, den = 0.f;
    for (int p = lo + j; p < hi; p += 4) {
        int s = g_csrc[p];
        float e = leakyf(g_als[s * HEADS + hd] + adh);
        g_alpha[(size_t)p * HEADS + hd] = e;
        if (e > m) { den = den * __expf(m - e) + 1.f; m = e; }
        else       { den += __expf(e - m); }
    }
#pragma unroll
    for (int off = 8; off <= 16; off <<= 1) {
        float mo = __shfl_xor_sync(0xffffffffu, m, off);
        float dn = __shfl_xor_sync(0xffffffffu, den, off);
        float mn = fmaxf(m, mo);
        float t1 = (m  == -INFINITY) ? 0.f : den * __expf(m - mn);
        float t2 = (mo == -INFINITY) ? 0.f : dn  * __expf(mo - mn);
        den = t1 + t2; m = mn;
    }
    float eself = leakyf(g_als[n * HEADS + hd] + adh);
    float mn = fmaxf(m, eself);
    den = ((m == -INFINITY) ? 0.f : den * __expf(m - mn)) + __expf(eself - mn);
    m = mn;
    float inv = 1.f / den;
    if (lane < 8) {
        g_aself[n * HEADS + hd] = __expf(eself - m) * inv;
        g_mx[n * HEADS + hd] = m;
        g_inv[n * HEADS + hd] = inv;
    }
}

// ---------------- zero per-graph pool ----------------------------------------
__global__ void k_zero_pool() {
    int i = blockIdx.x * blockDim.x + threadIdx.x;
    if (i < N_GRAPHS * 2048) g_pool[i] = 0.f;
}

// ---------------- layer-3 aggregation fused with graph pooling ---------------
// block = 256 threads handles 32 consecutive nodes (batch sorted); accumulates
// per-graph partial sums of agg[n, h*256+t]; flushes via atomicAdd at segment ends.
__global__ void k_aggH_pool(const float* __restrict__ h, const int* __restrict__ batch)
{
    int n0 = blockIdx.x * 32;
    int t = threadIdx.x;   // 256
    __shared__ float a_sm[32][HEADS];
    __shared__ int s_sm[32];
    __shared__ float m_s[HEADS], i_s[HEADS];
    int nend = min(n0 + 32, N_NODES);
    if (n0 >= N_NODES) return;
    float pacc[HEADS];
#pragma unroll
    for (int k = 0; k < HEADS; k++) pacc[k] = 0.f;
    int prevb = batch[n0];

    for (int n = n0; n < nend; n++) {
        int bn = batch[n];
        if (bn != prevb) {
#pragma unroll
            for (int k = 0; k < HEADS; k++) {
                atomicAdd(&g_pool[prevb * 2048 + k * 256 + t], pacc[k]);
                pacc[k] = 0.f;
            }
            prevb = bn;
        }
        __syncthreads();
        if (t < 8) { m_s[t] = g_mx[n * HEADS + t]; i_s[t] = g_inv[n * HEADS + t]; }
        __syncthreads();
        int lo = g_rowptr[n], hi = g_rowptr[n + 1];
        float hv = h[(size_t)n * 256 + t];
        float acc[HEADS];
#pragma unroll
        for (int k = 0; k < HEADS; k++)
            acc[k] = g_aself[n * HEADS + k] * hv;
        for (int p0 = lo; p0 < hi; p0 += 32) {
            int cnt = min(32, hi - p0);
            __syncthreads();
            if (t < cnt) s_sm[t] = g_csrc[p0 + t];
            if (t < cnt * HEADS) {
                float e = g_alpha[(size_t)p0 * HEADS + t];
                a_sm[t >> 3][t & 7] = __expf(e - m_s[t & 7]) * i_s[t & 7];
            }
            __syncthreads();
            for (int jj = 0; jj < cnt; jj++) {
                float hv2 = h[(size_t)s_sm[jj] * 256 + t];
#pragma unroll
                for (int k = 0; k < HEADS; k++)
                    acc[k] += a_sm[jj][k] * hv2;
            }
        }
#pragma unroll
        for (int k = 0; k < HEADS; k++) pacc[k] += acc[k];
    }
#pragma unroll
    for (int k = 0; k < HEADS; k++)
        atomicAdd(&g_pool[prevb * 2048 + k * 256 + t], pacc[k]);
}

// ---------------- layer-3 projection of pooled means -------------------------
__device__ __forceinline__ int lower_bound_batch(const int* b, int val) {
    int lo = 0, hi = N_NODES;
    while (lo < hi) {
        int mid = (lo + hi) >> 1;
        if (b[mid] < val) lo = mid + 1; else hi = mid;
    }
    return lo;
}
__global__ void k_out3(const float* __restrict__ W3, const float* __restrict__ b3,
                       const int* __restrict__ batch)
{
    int g = blockIdx.x;
    int d = threadIdx.x;  // 256
    int lo = lower_bound_batch(batch, g);
    int hi = lower_bound_batch(batch, g + 1);
    float cnt = (float)max(hi - lo, 1);
    float s = 0.f;
#pragma unroll
    for (int h = 0; h < HEADS; h++) {
        const float* wrow = W3 + (size_t)(h * 256 + d) * 256;
        const float* prow = g_pool + g * 2048 + h * 256;
        for (int k = 0; k < 256; k++) s += prow[k] * wrow[k];
    }
    g_gmean[g * 256 + d] = 0.125f * s / cnt + b3[d];
}

// ---------------- classifier MLP ---------------------------------------------
__global__ void k_classifier(const float* __restrict__ Wc1, const float* __restrict__ bc1,
                             const float* __restrict__ Wc2, const float* __restrict__ bc2,
                             float* __restrict__ out)
{
    int g = blockIdx.x;
    int t = threadIdx.x;  // 128
    __shared__ float z[128];
    const float* gr = g_gmean + g * 256;
    float s = bc1[t];
    for (int k = 0; k < 256; k++) s += gr[k] * Wc1[t * 256 + k];
    z[t] = eluf(s);
    __syncthreads();
    if (t < 2) {
        float o = bc2[t];
        for (int jj = 0; jj < 128; jj++) o += z[jj] * Wc2[t * 128 + jj];
        out[g * 2 + t] = o;
    }
}

// ---------------- launch -----------------------------------------------------
extern "C" void kernel_launch(void* const* d_in, const int* in_sizes, int n_in,
                              void* d_out, int out_size)
{
    const float* x      = (const float*)d_in[0];
    const int*   eidx   = (const int*)d_in[1];
    const int*   batch  = (const int*)d_in[2];
    const float* W1  = (const float*)d_in[3];
    const float* as1 = (const float*)d_in[4];
    const float* ad1 = (const float*)d_in[5];
    const float* b1  = (const float*)d_in[6];
    const float* W2  = (const float*)d_in[7];
    const float* as2 = (const float*)d_in[8];
    const float* ad2 = (const float*)d_in[9];
    const float* b2  = (const float*)d_in[10];
    const float* W3  = (const float*)d_in[11];
    const float* as3 = (const float*)d_in[12];
    const float* ad3 = (const float*)d_in[13];
    const float* b3  = (const float*)d_in[14];
    const float* Wc1 = (const float*)d_in[15];
    const float* bc1 = (const float*)d_in[16];
    const float* Wc2 = (const float*)d_in[17];
    const float* bc2 = (const float*)d_in[18];
    float* out = (float*)d_out;

    const int* src = eidx;
    const int* dst = eidx + N_EDGES;

    float* xp = nullptr; cudaGetSymbolAddress((void**)&xp, g_xp);
    float* h  = nullptr; cudaGetSymbolAddress((void**)&h,  g_h);
    float* xt = nullptr; cudaGetSymbolAddress((void**)&xt, g_xt);
    float* w1t = nullptr; cudaGetSymbolAddress((void**)&w1t, g_w1t);
    float* w2t = nullptr; cudaGetSymbolAddress((void**)&w2t, g_w2t);

    cudaFuncSetAttribute(k_mma2, cudaFuncAttributeMaxDynamicSharedMemorySize, GSM_BYTES);

    int gm = (N_NODES + 127) / 128;
    int nwb = (N_NODES + 7) / 8;

    // ordered so the 6th launch (ncu -s 5 -c 1) is the layer-1 tf32 MMA GEMM
    k_round<<<(N_NODES * 32 + 255) / 256, 256>>>(x, xt, N_NODES * 32);     // 1
    k_round<<<(256 * 32 + 255) / 256, 256>>>(W1, w1t, 256 * 32);           // 2
    k_zero_deg<<<(N_NODES + 255) / 256, 256>>>();                          // 3
    k_hist<<<(N_EDGES + 255) / 256, 256>>>(dst);                           // 4
    k_scan<<<1, 1024>>>();                                                 // 5
    k_mma2<<<gm, 256, GSM_BYTES>>>(xt, w1t, xp, nullptr, N_NODES, 32);     // 6 (profiled)
    k_scatter<<<(N_EDGES + 255) / 256, 256>>>(src, dst);                   // 7
    k_round<<<(256 * 256 + 255) / 256, 256>>>(W2, w2t, 256 * 256);         // 8
    k_fold3<<<(2048 + 127) / 128, 128>>>(W3, as3, ad3);                    // 9
    k_zero_pool<<<(N_GRAPHS * 2048 + 255) / 256, 256>>>();                 // 10

    // ---- layer 1: GATConv(32 -> 8x32, concat) + ELU (fused softmax+agg)
    k_al<<<N_NODES, 256>>>(xp, as1, ad1);
    k_gat32<<<nwb, 256>>>(xp, b1, h);

    // ---- layer 2
    k_mma2<<<gm, 256, GSM_BYTES>>>(h, w2t, xp, nullptr, N_NODES, 256);
    k_al<<<N_NODES, 256>>>(xp, as2, ad2);
    k_gat32<<<nwb, 256>>>(xp, b2, h);

    // ---- layer 3: al from folded vectors, softmax, agg fused with pooling,
    //      then project pooled means (52 GF GEMM eliminated)
    k_al3<<<N_NODES, 256>>>(h);
    k_softmax<<<nwb, 256>>>();
    k_aggH_pool<<<(N_NODES + 31) / 32, 256>>>(h, batch);
    k_out3<<<N_GRAPHS, 256>>>(W3, b3, batch);

    // ---- classifier
    k_classifier<<<N_GRAPHS, 128>>>(Wc1, bc1, Wc2, bc2, out);
}